// round 13
// baseline (speedup 1.0000x reference)
#include <cuda_runtime.h>
#include <cuda_bf16.h>
#include <math.h>
#include <cstdint>

// Shape fixed by dataset: B=16, N=1024, E=128, kv row = 2E+1 = 257
#define BATCH   16
#define NATOMS  1024
#define EDIM    128
#define KVROW   257
#define TI      64
#define TJ      64
#define NTILES  16
#define THREADS 512

// Pre-split bf16 operands, packed 2 per uint32: [b][n][pair] (64 pairs/row)
__device__ uint32_t g_khi[BATCH * NATOMS * 64];
__device__ uint32_t g_klo[BATCH * NATOMS * 64];
__device__ uint32_t g_vhi[BATCH * NATOMS * 64];
__device__ uint32_t g_vlo[BATCH * NATOMS * 64];

// Operand rows padded to 272 B (ldmatrix conflict-free without swizzle).
#define STRIDE_B 272
#define TILE_B   (64 * STRIDE_B)         // 17408 per 64-row buffer

#define OFF_AHI  0
#define OFF_ALO  17408
#define OFF_B0HI 34816
#define OFF_B0LO 52224
#define OFF_B1HI 69632
#define OFF_B1LO 87040
#define OFF_PQ   104448                  // 4 stages x 64 x 16B = 4096
#define OFF_RED  108544                  // 4 col-groups x 64 rows x 3 floats
#define OFF_MS   111616                  // 16 floats
#define SMEM_BYTES 111744                // x2 blocks = 223488 <= 233472/SM

__device__ __forceinline__ uint32_t smem_u32(const void* p) {
    uint32_t a;
    asm("{ .reg .u64 t; cvta.to.shared.u64 t, %1; cvt.u32.u64 %0, t; }"
        : "=r"(a) : "l"(p));
    return a;
}
__device__ __forceinline__ void cpa16(uint32_t dst, const void* src) {
    asm volatile("cp.async.cg.shared.global [%0], [%1], 16;" :: "r"(dst), "l"(src));
}
__device__ __forceinline__ void cpa4(uint32_t dst, const void* src) {
    asm volatile("cp.async.ca.shared.global [%0], [%1], 4;" :: "r"(dst), "l"(src));
}
#define CP_COMMIT() asm volatile("cp.async.commit_group;" ::: "memory")
#define CP_WAIT0()  asm volatile("cp.async.wait_group 0;" ::: "memory")

#define LDSM4(r, addr)                                                      \
    asm volatile("ldmatrix.sync.aligned.m8n8.x4.shared.b16 {%0,%1,%2,%3}, [%4];" \
        : "=r"((r)[0]), "=r"((r)[1]), "=r"((r)[2]), "=r"((r)[3]) : "r"(addr))

#define MMA_BF16(c, a, b0_, b1_)                                            \
    asm volatile("mma.sync.aligned.m16n8k16.row.col.f32.bf16.bf16.f32 "     \
        "{%0,%1,%2,%3}, {%4,%5,%6,%7}, {%8,%9}, {%0,%1,%2,%3};"             \
        : "+f"((c)[0]), "+f"((c)[1]), "+f"((c)[2]), "+f"((c)[3])            \
        : "r"((a)[0]), "r"((a)[1]), "r"((a)[2]), "r"((a)[3]),               \
          "r"(b0_), "r"(b1_))

// ---------------- prepass: fp32 -> bf16 hi/lo split, packed pairs ----------
__global__ __launch_bounds__(256)
void split_kv_kernel(const float* __restrict__ kv,
                     const float* __restrict__ mask)
{
    int idx = blockIdx.x * 256 + threadIdx.x;        // [0, B*N*64)
    if (idx >= BATCH * NATOMS * 64) return;
    int p = idx & 63;
    int n = (idx >> 6) & (NATOMS - 1);
    int b = idx >> 16;

    const float* row = kv + ((size_t)b * NATOMS + n) * KVROW;
    float m  = mask[b * NATOMS + n];
    float mk = m * 0.088388347648318447f;            // mask * 1/sqrt(128)

    float k0 = row[2 * p] * mk,        k1 = row[2 * p + 1] * mk;
    float v0 = row[EDIM + 2 * p] * m,  v1 = row[EDIM + 2 * p + 1] * m;

    __nv_bfloat16 kh0 = __float2bfloat16(k0), kh1 = __float2bfloat16(k1);
    __nv_bfloat16 kl0 = __float2bfloat16(k0 - __bfloat162float(kh0));
    __nv_bfloat16 kl1 = __float2bfloat16(k1 - __bfloat162float(kh1));
    __nv_bfloat16 vh0 = __float2bfloat16(v0), vh1 = __float2bfloat16(v1);
    __nv_bfloat16 vl0 = __float2bfloat16(v0 - __bfloat162float(vh0));
    __nv_bfloat16 vl1 = __float2bfloat16(v1 - __bfloat162float(vh1));

    g_khi[idx] = (uint32_t)__bfloat16_as_ushort(kh0) | ((uint32_t)__bfloat16_as_ushort(kh1) << 16);
    g_klo[idx] = (uint32_t)__bfloat16_as_ushort(kl0) | ((uint32_t)__bfloat16_as_ushort(kl1) << 16);
    g_vhi[idx] = (uint32_t)__bfloat16_as_ushort(vh0) | ((uint32_t)__bfloat16_as_ushort(vh1) << 16);
    g_vlo[idx] = (uint32_t)__bfloat16_as_ushort(vl0) | ((uint32_t)__bfloat16_as_ushort(vl1) << 16);
}

// ---------------- main kernel: 16 warps, 4x4 grid of 16x16 warp tiles ------
__global__ __launch_bounds__(THREADS, 2)
void gen_actions_kernel(const float* __restrict__ pos,
                        const float* __restrict__ mask,
                        const float* __restrict__ ascale,
                        float* __restrict__ out)
{
    extern __shared__ char sp[];
    const uint32_t sb = smem_u32(sp);

    const int tid  = threadIdx.x;
    const int wid  = tid >> 5;
    const int lane = tid & 31;
    const int wr   = wid & 3;       // warp rows [16wr, 16wr+16)
    const int wc   = wid >> 2;      // warp cols [16wc, 16wc+16)
    const int qid  = lane >> 2;
    const int qe   = lane & 3;

    const int b  = blockIdx.y;
    const int i0 = blockIdx.x * TI;

    const float* mb = mask + (size_t)b * NATOMS;
    const float* pb = pos  + (size_t)b * NATOMS * 3;

    // ---- prologue: A hi/lo + B tile 0 hi/lo + pos stage 0, ONE group ----
    {
        const uint32_t* ah = g_khi + ((size_t)b * NATOMS + i0) * 64;
        const uint32_t* al = g_klo + ((size_t)b * NATOMS + i0) * 64;
        const uint32_t* bh = g_vhi + (size_t)b * NATOMS * 64;   // jt = 0
        const uint32_t* bl = g_vlo + (size_t)b * NATOMS * 64;
        #pragma unroll
        for (int it = 0; it < 2; it++) {
            int idx = tid + it * THREADS;            // [0,1024)
            int r = idx >> 4, c = idx & 15;
            cpa16(sb + OFF_AHI  + r * STRIDE_B + c * 16, ah + r * 64 + c * 4);
            cpa16(sb + OFF_ALO  + r * STRIDE_B + c * 16, al + r * 64 + c * 4);
            cpa16(sb + OFF_B0HI + r * STRIDE_B + c * 16, bh + r * 64 + c * 4);
            cpa16(sb + OFF_B0LO + r * STRIDE_B + c * 16, bl + r * 64 + c * 4);
        }
        if (tid < 192) {   // 64 rows x 3 comps
            int r = tid / 3, cmp = tid - 3 * r;
            cpa4(sb + OFF_PQ + r * 16 + cmp * 4, pb + r * 3 + cmp);
        }
        CP_COMMIT();
    }

    // ---- mask sum (overlaps the async loads) ----
    {
        float* sMS = (float*)(sp + OFF_MS);
        float ms = 0.f;
        for (int n = tid; n < NATOMS; n += THREADS) ms += mb[n];
        #pragma unroll
        for (int off = 16; off > 0; off >>= 1)
            ms += __shfl_xor_sync(0xFFFFFFFFu, ms, off);
        if (lane == 0) sMS[wid] = ms;
    }
    __syncthreads();
    float msum = 0.f;
    {
        float* sMS = (float*)(sp + OFF_MS);
        #pragma unroll
        for (int q = 0; q < 16; q++) msum += sMS[q];
    }
    const float inv_msum = 1.0f / msum;
    const float as = ascale[0];

    // ---- this thread's 2 fixed rows: 16wr + qid, 16wr + qid + 8 ----
    const int gr0 = i0 + 16 * wr + qid;
    const int gr1 = gr0 + 8;
    const float p0x = pb[(size_t)gr0 * 3 + 0];
    const float p0y = pb[(size_t)gr0 * 3 + 1];
    const float p0z = pb[(size_t)gr0 * 3 + 2];
    const float p1x = pb[(size_t)gr1 * 3 + 0];
    const float p1y = pb[(size_t)gr1 * 3 + 1];
    const float p1z = pb[(size_t)gr1 * 3 + 2];

    // ---- ldmatrix lane base addresses (conflict-free) ----
    const uint32_t aRow = 16 * wr + (lane & 15);
    const uint32_t aKof = (lane & 16) ? 16u : 0u;
    const uint32_t aHiB = sb + OFF_AHI + aRow * STRIDE_B + aKof;
    const uint32_t aLoB = sb + OFF_ALO + aRow * STRIDE_B + aKof;
    const uint32_t bRow = 16 * wc + (lane & 7) + ((lane & 16) ? 8 : 0);
    const uint32_t bKof = (lane & 8) ? 16u : 0u;
    const uint32_t bLaneOff = bRow * STRIDE_B + bKof;

    float a0x = 0.f, a0y = 0.f, a0z = 0.f;
    float a1x = 0.f, a1y = 0.f, a1z = 0.f;

    for (int t = 0; t < NTILES; t++) {
        CP_WAIT0();
        __syncthreads();
        if (t + 1 < NTILES) {
            const int jn = (t + 1) * TJ;
            const uint32_t hiN = ((t + 1) & 1) ? OFF_B1HI : OFF_B0HI;
            const uint32_t loN = ((t + 1) & 1) ? OFF_B1LO : OFF_B0LO;
            const uint32_t* bh = g_vhi + ((size_t)b * NATOMS + jn) * 64;
            const uint32_t* bl = g_vlo + ((size_t)b * NATOMS + jn) * 64;
            #pragma unroll
            for (int it = 0; it < 2; it++) {
                int idx = tid + it * THREADS;
                int r = idx >> 4, c = idx & 15;
                cpa16(sb + hiN + r * STRIDE_B + c * 16, bh + r * 64 + c * 4);
                cpa16(sb + loN + r * STRIDE_B + c * 16, bl + r * 64 + c * 4);
            }
            if (tid < 192) {
                int r = tid / 3, cmp = tid - 3 * r;
                cpa4(sb + OFF_PQ + (((t + 1) & 3) * 64 + r) * 16 + cmp * 4,
                     pb + (jn + r) * 3 + cmp);
            }
            CP_COMMIT();
        }

        const uint32_t bHiB = sb + ((t & 1) ? OFF_B1HI : OFF_B0HI) + bLaneOff;
        const uint32_t bLoB = sb + ((t & 1) ? OFF_B1LO : OFF_B0LO) + bLaneOff;

        // ---- GEMM 16x16 per warp: 3-pass bf16 split ----
        float C[2][4];
        #pragma unroll
        for (int nt = 0; nt < 2; nt++)
            #pragma unroll
            for (int e = 0; e < 4; e++) C[nt][e] = 0.f;

        #pragma unroll
        for (int kc = 0; kc < 8; kc++) {
            uint32_t ah[4], al[4], bh[4], bl[4];
            uint32_t ko = kc * 32;
            LDSM4(ah, aHiB + ko);
            LDSM4(al, aLoB + ko);
            LDSM4(bh, bHiB + ko);
            LDSM4(bl, bLoB + ko);
            MMA_BF16(C[0], ah, bh[0], bh[1]);
            MMA_BF16(C[1], ah, bh[2], bh[3]);
            MMA_BF16(C[0], ah, bl[0], bl[1]);
            MMA_BF16(C[1], ah, bl[2], bl[3]);
            MMA_BF16(C[0], al, bh[0], bh[1]);
            MMA_BF16(C[1], al, bh[2], bh[3]);
        }

        // ---- fused epilogue ----
        const float4* sQ = (const float4*)(sp + OFF_PQ + (t & 3) * 1024);
        #pragma unroll
        for (int nt = 0; nt < 2; nt++)
            #pragma unroll
            for (int e = 0; e < 2; e++) {
                float4 q = sQ[16 * wc + 8 * nt + 2 * qe + e];
                // row 0 (qid)
                {
                    float dx = p0x - q.x, dy = p0y - q.y, dz = p0z - q.z;
                    float d2 = fmaf(dx, dx, fmaf(dy, dy, dz * dz));
                    float inv = rsqrtf(fmaxf(d2, 1e-36f));   // diag -> 0
                    float w = C[nt][e] * inv;
                    a0x = fmaf(w, dx, a0x);
                    a0y = fmaf(w, dy, a0y);
                    a0z = fmaf(w, dz, a0z);
                }
                // row 1 (qid+8)
                {
                    float dx = p1x - q.x, dy = p1y - q.y, dz = p1z - q.z;
                    float d2 = fmaf(dx, dx, fmaf(dy, dy, dz * dz));
                    float inv = rsqrtf(fmaxf(d2, 1e-36f));
                    float w = C[nt][2 + e] * inv;
                    a1x = fmaf(w, dx, a1x);
                    a1y = fmaf(w, dy, a1y);
                    a1z = fmaf(w, dz, a1z);
                }
            }
    }

    // ---- reduce over qe lanes (bits 0,1): sums this warp's 16 cols ----
    #pragma unroll
    for (int off = 1; off < 4; off <<= 1) {
        a0x += __shfl_xor_sync(0xFFFFFFFFu, a0x, off);
        a0y += __shfl_xor_sync(0xFFFFFFFFu, a0y, off);
        a0z += __shfl_xor_sync(0xFFFFFFFFu, a0z, off);
        a1x += __shfl_xor_sync(0xFFFFFFFFu, a1x, off);
        a1y += __shfl_xor_sync(0xFFFFFFFFu, a1y, off);
        a1z += __shfl_xor_sync(0xFFFFFFFFu, a1z, off);
    }

    __syncthreads();
    float* sRed = (float*)(sp + OFF_RED);    // [4 col-groups][64 rows][3]
    if (qe == 0) {
        int r0 = 16 * wr + qid;
        float* d0 = sRed + (wc * 64 + r0) * 3;
        d0[0] = a0x; d0[1] = a0y; d0[2] = a0z;
        float* d1 = sRed + (wc * 64 + r0 + 8) * 3;
        d1[0] = a1x; d1[1] = a1y; d1[2] = a1z;
    }
    __syncthreads();

    if (tid < TI) {
        int gi = i0 + tid;
        float sx = 0.f, sy = 0.f, sz = 0.f;
        #pragma unroll
        for (int g = 0; g < 4; g++) {
            const float* d = sRed + (g * 64 + tid) * 3;
            sx += d[0]; sy += d[1]; sz += d[2];
        }
        float s = as * mb[gi];
        float* o = out + ((size_t)b * NATOMS + gi) * 3;
        o[0] = tanhf(sx * inv_msum) * s;
        o[1] = tanhf(sy * inv_msum) * s;
        o[2] = tanhf(sz * inv_msum) * s;
    }
}

extern "C" void kernel_launch(void* const* d_in, const int* in_sizes, int n_in,
                              void* d_out, int out_size) {
    const float* kv   = (const float*)d_in[0];
    const float* pos  = (const float*)d_in[1];
    const float* mask = (const float*)d_in[2];
    const float* asc  = (const float*)d_in[3];
    float* out = (float*)d_out;

    cudaFuncSetAttribute(gen_actions_kernel,
                         cudaFuncAttributeMaxDynamicSharedMemorySize,
                         (int)SMEM_BYTES);

    split_kv_kernel<<<(BATCH * NATOMS * 64 + 255) / 256, 256>>>(kv, mask);

    dim3 grid(NATOMS / TI, BATCH);   // 16 x 16 = 256 blocks, 2 per SM
    gen_actions_kernel<<<grid, THREADS, SMEM_BYTES>>>(pos, mask, asc, out);
}

// round 14
// speedup vs baseline: 1.1467x; 1.1467x over previous
#include <cuda_runtime.h>
#include <cuda_bf16.h>
#include <math.h>
#include <cstdint>

// Shape fixed by dataset: B=16, N=1024, E=128, kv row = 2E+1 = 257
#define BATCH   16
#define NATOMS  1024
#define EDIM    128
#define KVROW   257
#define TI      128
#define TJ      64
#define NTILES  16
#define THREADS 512

// Pre-split bf16 operands, packed 2 per uint32: [b][n][pair] (64 pairs/row)
__device__ uint32_t g_khi[BATCH * NATOMS * 64];
__device__ uint32_t g_klo[BATCH * NATOMS * 64];
__device__ uint32_t g_vhi[BATCH * NATOMS * 64];
__device__ uint32_t g_vlo[BATCH * NATOMS * 64];

// Operand rows padded to 272 B (ldmatrix conflict-free without swizzle).
#define STRIDE_B 272

#define OFF_AHI  0                       // 128*272 = 34816
#define OFF_ALO  34816
#define OFF_B0HI 69632                   // 64*272 = 17408 each
#define OFF_B0LO 87040
#define OFF_B1HI 104448
#define OFF_B1LO 121856
#define OFF_PQ   139264                  // 4 stages x 64 x 16B = 4096
#define OFF_RED  143360                  // 4 col-groups x 128 rows x 3 floats
#define OFF_MS   149504                  // 16 floats
#define SMEM_BYTES 149568                // 1 block/SM

__device__ __forceinline__ uint32_t smem_u32(const void* p) {
    uint32_t a;
    asm("{ .reg .u64 t; cvta.to.shared.u64 t, %1; cvt.u32.u64 %0, t; }"
        : "=r"(a) : "l"(p));
    return a;
}
__device__ __forceinline__ void cpa16(uint32_t dst, const void* src) {
    asm volatile("cp.async.cg.shared.global [%0], [%1], 16;" :: "r"(dst), "l"(src));
}
__device__ __forceinline__ void cpa4(uint32_t dst, const void* src) {
    asm volatile("cp.async.ca.shared.global [%0], [%1], 4;" :: "r"(dst), "l"(src));
}
#define CP_COMMIT() asm volatile("cp.async.commit_group;" ::: "memory")
#define CP_WAIT0()  asm volatile("cp.async.wait_group 0;" ::: "memory")

#define LDSM4(r, addr)                                                      \
    asm volatile("ldmatrix.sync.aligned.m8n8.x4.shared.b16 {%0,%1,%2,%3}, [%4];" \
        : "=r"((r)[0]), "=r"((r)[1]), "=r"((r)[2]), "=r"((r)[3]) : "r"(addr))

#define MMA_BF16(c, a, b0_, b1_)                                            \
    asm volatile("mma.sync.aligned.m16n8k16.row.col.f32.bf16.bf16.f32 "     \
        "{%0,%1,%2,%3}, {%4,%5,%6,%7}, {%8,%9}, {%0,%1,%2,%3};"             \
        : "+f"((c)[0]), "+f"((c)[1]), "+f"((c)[2]), "+f"((c)[3])            \
        : "r"((a)[0]), "r"((a)[1]), "r"((a)[2]), "r"((a)[3]),               \
          "r"(b0_), "r"(b1_))

// ---------------- prepass: fp32 -> bf16 hi/lo split, packed pairs ----------
__global__ __launch_bounds__(256)
void split_kv_kernel(const float* __restrict__ kv,
                     const float* __restrict__ mask)
{
    int idx = blockIdx.x * 256 + threadIdx.x;        // [0, B*N*64)
    if (idx >= BATCH * NATOMS * 64) return;
    int p = idx & 63;
    int n = (idx >> 6) & (NATOMS - 1);
    int b = idx >> 16;

    const float* row = kv + ((size_t)b * NATOMS + n) * KVROW;
    float m  = mask[b * NATOMS + n];
    float mk = m * 0.088388347648318447f;            // mask * 1/sqrt(128)

    float k0 = row[2 * p] * mk,        k1 = row[2 * p + 1] * mk;
    float v0 = row[EDIM + 2 * p] * m,  v1 = row[EDIM + 2 * p + 1] * m;

    __nv_bfloat16 kh0 = __float2bfloat16(k0), kh1 = __float2bfloat16(k1);
    __nv_bfloat16 kl0 = __float2bfloat16(k0 - __bfloat162float(kh0));
    __nv_bfloat16 kl1 = __float2bfloat16(k1 - __bfloat162float(kh1));
    __nv_bfloat16 vh0 = __float2bfloat16(v0), vh1 = __float2bfloat16(v1);
    __nv_bfloat16 vl0 = __float2bfloat16(v0 - __bfloat162float(vh0));
    __nv_bfloat16 vl1 = __float2bfloat16(v1 - __bfloat162float(vh1));

    g_khi[idx] = (uint32_t)__bfloat16_as_ushort(kh0) | ((uint32_t)__bfloat16_as_ushort(kh1) << 16);
    g_klo[idx] = (uint32_t)__bfloat16_as_ushort(kl0) | ((uint32_t)__bfloat16_as_ushort(kl1) << 16);
    g_vhi[idx] = (uint32_t)__bfloat16_as_ushort(vh0) | ((uint32_t)__bfloat16_as_ushort(vh1) << 16);
    g_vlo[idx] = (uint32_t)__bfloat16_as_ushort(vl0) | ((uint32_t)__bfloat16_as_ushort(vl1) << 16);
}

// one epilogue element of the OLD C tile: ec in [0,16)
__device__ __forceinline__ void epi_one(int ec, const float (&Co)[2][2][4],
    const float4* sQ, int wc, int qe,
    const float (&pix)[4], const float (&piy)[4], const float (&piz)[4],
    float (&ax)[4], float (&ay)[4], float (&az)[4])
{
    const int mt = ec >> 3, nt = (ec >> 2) & 1, h = (ec >> 1) & 1, e = ec & 1;
    const int ridx = 2 * mt + h;
    float4 q = sQ[16 * wc + 8 * nt + 2 * qe + e];
    float dx = pix[ridx] - q.x;
    float dy = piy[ridx] - q.y;
    float dz = piz[ridx] - q.z;
    float d2 = fmaf(dx, dx, fmaf(dy, dy, dz * dz));
    float inv = rsqrtf(fmaxf(d2, 1e-36f));      // diagonal -> 0 contribution
    float w = Co[mt][nt][2 * h + e] * inv;
    ax[ridx] = fmaf(w, dx, ax[ridx]);
    ay[ridx] = fmaf(w, dy, ay[ridx]);
    az[ridx] = fmaf(w, dz, az[ridx]);
}

// One tile: wait B(t), refill B(t+1), GEMM tile t into Cn with epilogue of
// tile t-1 (Co) interleaved between k-chunks.
template<bool DO_OLD>
__device__ __forceinline__ void tile_step(int t, int b,
    float (&Cn)[2][2][4], float (&Co)[2][2][4],
    uint32_t sb, const char* sp, int tid,
    uint32_t aHiB, uint32_t aLoB, uint32_t bLaneOff,
    const float* pb, int wc, int qe,
    const float (&pix)[4], const float (&piy)[4], const float (&piz)[4],
    float (&ax)[4], float (&ay)[4], float (&az)[4])
{
    CP_WAIT0();
    __syncthreads();
    if (t + 1 < NTILES) {
        const int jn = (t + 1) * TJ;
        const uint32_t hiN = ((t + 1) & 1) ? OFF_B1HI : OFF_B0HI;
        const uint32_t loN = ((t + 1) & 1) ? OFF_B1LO : OFF_B0LO;
        const uint32_t* bh = g_vhi + ((size_t)b * NATOMS + jn) * 64;
        const uint32_t* bl = g_vlo + ((size_t)b * NATOMS + jn) * 64;
        #pragma unroll
        for (int it = 0; it < 2; it++) {
            int idx = tid + it * THREADS;            // [0,1024)
            int r = idx >> 4, c = idx & 15;
            cpa16(sb + hiN + r * STRIDE_B + c * 16, bh + r * 64 + c * 4);
            cpa16(sb + loN + r * STRIDE_B + c * 16, bl + r * 64 + c * 4);
        }
        if (tid < 192) {
            int r = tid / 3, cmp = tid - 3 * r;
            cpa4(sb + OFF_PQ + (((t + 1) & 3) * 64 + r) * 16 + cmp * 4,
                 pb + (jn + r) * 3 + cmp);
        }
        CP_COMMIT();
    }

    const uint32_t bHiB = sb + ((t & 1) ? OFF_B1HI : OFF_B0HI) + bLaneOff;
    const uint32_t bLoB = sb + ((t & 1) ? OFF_B1LO : OFF_B0LO) + bLaneOff;
    const float4* sQold = (const float4*)(sp + OFF_PQ + ((t - 1) & 3) * 1024);

    #pragma unroll
    for (int mt = 0; mt < 2; mt++)
        #pragma unroll
        for (int nt = 0; nt < 2; nt++)
            #pragma unroll
            for (int e = 0; e < 4; e++) Cn[mt][nt][e] = 0.f;

    #pragma unroll
    for (int kc = 0; kc < 8; kc++) {
        uint32_t ah[2][4], al[2][4], bh[4], bl[4];
        const uint32_t ko = kc * 32;
        #pragma unroll
        for (int mt = 0; mt < 2; mt++) {
            uint32_t o = mt * (16 * STRIDE_B) + ko;
            LDSM4(ah[mt], aHiB + o);
            LDSM4(al[mt], aLoB + o);
        }
        LDSM4(bh, bHiB + ko);
        LDSM4(bl, bLoB + ko);

        // 12 MMAs (3-pass split), epilogue elems of old tile slotted between
        #pragma unroll
        for (int mt = 0; mt < 2; mt++) {
            MMA_BF16(Cn[mt][0], ah[mt], bh[0], bh[1]);
            MMA_BF16(Cn[mt][1], ah[mt], bh[2], bh[3]);
        }
        if (DO_OLD) epi_one(2 * kc, Co, sQold, wc, qe, pix, piy, piz, ax, ay, az);
        #pragma unroll
        for (int mt = 0; mt < 2; mt++) {
            MMA_BF16(Cn[mt][0], ah[mt], bl[0], bl[1]);
            MMA_BF16(Cn[mt][1], ah[mt], bl[2], bl[3]);
        }
        if (DO_OLD) epi_one(2 * kc + 1, Co, sQold, wc, qe, pix, piy, piz, ax, ay, az);
        #pragma unroll
        for (int mt = 0; mt < 2; mt++) {
            MMA_BF16(Cn[mt][0], al[mt], bh[0], bh[1]);
            MMA_BF16(Cn[mt][1], al[mt], bh[2], bh[3]);
        }
    }
}

// ---------------- main kernel: 16 warps, 4x4 grid of 32x16 warp tiles ------
__global__ __launch_bounds__(THREADS, 1)
void gen_actions_kernel(const float* __restrict__ pos,
                        const float* __restrict__ mask,
                        const float* __restrict__ ascale,
                        float* __restrict__ out)
{
    extern __shared__ char sp[];
    const uint32_t sb = smem_u32(sp);

    const int tid  = threadIdx.x;
    const int wid  = tid >> 5;
    const int lane = tid & 31;
    const int wr   = wid & 3;       // warp rows [32wr, 32wr+32)
    const int wc   = wid >> 2;      // warp cols [16wc, 16wc+16)
    const int qid  = lane >> 2;
    const int qe   = lane & 3;

    const int b  = blockIdx.y;
    const int i0 = blockIdx.x * TI;

    const float* mb = mask + (size_t)b * NATOMS;
    const float* pb = pos  + (size_t)b * NATOMS * 3;

    // ---- prologue: A hi/lo + B tile 0 hi/lo + pos stage 0, ONE group ----
    {
        const uint32_t* ah = g_khi + ((size_t)b * NATOMS + i0) * 64;
        const uint32_t* al = g_klo + ((size_t)b * NATOMS + i0) * 64;
        #pragma unroll
        for (int it = 0; it < 4; it++) {
            int idx = tid + it * THREADS;            // [0,2048)
            int r = idx >> 4, c = idx & 15;
            cpa16(sb + OFF_AHI + r * STRIDE_B + c * 16, ah + r * 64 + c * 4);
            cpa16(sb + OFF_ALO + r * STRIDE_B + c * 16, al + r * 64 + c * 4);
        }
        const uint32_t* bh = g_vhi + (size_t)b * NATOMS * 64;   // jt = 0
        const uint32_t* bl = g_vlo + (size_t)b * NATOMS * 64;
        #pragma unroll
        for (int it = 0; it < 2; it++) {
            int idx = tid + it * THREADS;            // [0,1024)
            int r = idx >> 4, c = idx & 15;
            cpa16(sb + OFF_B0HI + r * STRIDE_B + c * 16, bh + r * 64 + c * 4);
            cpa16(sb + OFF_B0LO + r * STRIDE_B + c * 16, bl + r * 64 + c * 4);
        }
        if (tid < 192) {
            int r = tid / 3, cmp = tid - 3 * r;
            cpa4(sb + OFF_PQ + r * 16 + cmp * 4, pb + r * 3 + cmp);
        }
        CP_COMMIT();
    }

    // ---- mask sum (overlaps the async loads) ----
    {
        float* sMS = (float*)(sp + OFF_MS);
        float ms = 0.f;
        for (int n = tid; n < NATOMS; n += THREADS) ms += mb[n];
        #pragma unroll
        for (int off = 16; off > 0; off >>= 1)
            ms += __shfl_xor_sync(0xFFFFFFFFu, ms, off);
        if (lane == 0) sMS[wid] = ms;
    }
    __syncthreads();
    float msum = 0.f;
    {
        float* sMS = (float*)(sp + OFF_MS);
        #pragma unroll
        for (int q = 0; q < 16; q++) msum += sMS[q];
    }
    const float inv_msum = 1.0f / msum;
    const float as = ascale[0];

    // ---- this thread's 4 fixed rows: 32wr + 16mt + 8h + qid ----
    float pix[4], piy[4], piz[4];
    #pragma unroll
    for (int mt = 0; mt < 2; mt++)
        #pragma unroll
        for (int h = 0; h < 2; h++) {
            int gi = i0 + 32 * wr + 16 * mt + 8 * h + qid;
            const float* p = pb + (size_t)gi * 3;
            pix[2 * mt + h] = p[0]; piy[2 * mt + h] = p[1]; piz[2 * mt + h] = p[2];
        }

    // ---- ldmatrix lane base addresses (conflict-free) ----
    const uint32_t aRow = 32 * wr + (lane & 15);
    const uint32_t aKof = (lane & 16) ? 16u : 0u;
    const uint32_t aHiB = sb + OFF_AHI + aRow * STRIDE_B + aKof;
    const uint32_t aLoB = sb + OFF_ALO + aRow * STRIDE_B + aKof;
    const uint32_t bRow = 16 * wc + (lane & 7) + ((lane & 16) ? 8 : 0);
    const uint32_t bKof = (lane & 8) ? 16u : 0u;
    const uint32_t bLaneOff = bRow * STRIDE_B + bKof;

    float ax[4], ay[4], az[4];
    #pragma unroll
    for (int r = 0; r < 4; r++) { ax[r] = 0.f; ay[r] = 0.f; az[r] = 0.f; }

    float Ca[2][2][4], Cb[2][2][4];

    // peel first pair (tile 0 has no previous epilogue)
    tile_step<false>(0, b, Ca, Cb, sb, sp, tid, aHiB, aLoB, bLaneOff,
                     pb, wc, qe, pix, piy, piz, ax, ay, az);
    tile_step<true>(1, b, Cb, Ca, sb, sp, tid, aHiB, aLoB, bLaneOff,
                    pb, wc, qe, pix, piy, piz, ax, ay, az);
    for (int tp = 2; tp < NTILES; tp += 2) {
        tile_step<true>(tp, b, Ca, Cb, sb, sp, tid, aHiB, aLoB, bLaneOff,
                        pb, wc, qe, pix, piy, piz, ax, ay, az);
        tile_step<true>(tp + 1, b, Cb, Ca, sb, sp, tid, aHiB, aLoB, bLaneOff,
                        pb, wc, qe, pix, piy, piz, ax, ay, az);
    }
    // tail: epilogue of tile 15 (in Cb), pos stage 15&3 = 3
    {
        const float4* sQ = (const float4*)(sp + OFF_PQ + 3 * 1024);
        #pragma unroll
        for (int ec = 0; ec < 16; ec++)
            epi_one(ec, Cb, sQ, wc, qe, pix, piy, piz, ax, ay, az);
    }

    // ---- reduce over qe lanes (bits 0,1): sums this warp's 16 cols ----
    #pragma unroll
    for (int off = 1; off < 4; off <<= 1)
        #pragma unroll
        for (int r = 0; r < 4; r++) {
            ax[r] += __shfl_xor_sync(0xFFFFFFFFu, ax[r], off);
            ay[r] += __shfl_xor_sync(0xFFFFFFFFu, ay[r], off);
            az[r] += __shfl_xor_sync(0xFFFFFFFFu, az[r], off);
        }

    __syncthreads();
    float* sRed = (float*)(sp + OFF_RED);    // [4 col-groups][128 rows][3]
    if (qe == 0) {
        #pragma unroll
        for (int mt = 0; mt < 2; mt++)
            #pragma unroll
            for (int h = 0; h < 2; h++) {
                int row = 32 * wr + 16 * mt + 8 * h + qid;
                float* d = sRed + (wc * 128 + row) * 3;
                int ridx = 2 * mt + h;
                d[0] = ax[ridx]; d[1] = ay[ridx]; d[2] = az[ridx];
            }
    }
    __syncthreads();

    if (tid < TI) {
        int gi = i0 + tid;
        float sx = 0.f, sy = 0.f, sz = 0.f;
        #pragma unroll
        for (int g = 0; g < 4; g++) {
            const float* d = sRed + (g * 128 + tid) * 3;
            sx += d[0]; sy += d[1]; sz += d[2];
        }
        float s = as * mb[gi];
        float* o = out + ((size_t)b * NATOMS + gi) * 3;
        o[0] = tanhf(sx * inv_msum) * s;
        o[1] = tanhf(sy * inv_msum) * s;
        o[2] = tanhf(sz * inv_msum) * s;
    }
}

extern "C" void kernel_launch(void* const* d_in, const int* in_sizes, int n_in,
                              void* d_out, int out_size) {
    const float* kv   = (const float*)d_in[0];
    const float* pos  = (const float*)d_in[1];
    const float* mask = (const float*)d_in[2];
    const float* asc  = (const float*)d_in[3];
    float* out = (float*)d_out;

    cudaFuncSetAttribute(gen_actions_kernel,
                         cudaFuncAttributeMaxDynamicSharedMemorySize,
                         (int)SMEM_BYTES);

    split_kv_kernel<<<(BATCH * NATOMS * 64 + 255) / 256, 256>>>(kv, mask);

    dim3 grid(NATOMS / TI, BATCH);   // 8 x 16 = 128 blocks, one wave
    gen_actions_kernel<<<grid, THREADS, SMEM_BYTES>>>(pos, mask, asc, out);
}

// round 15
// speedup vs baseline: 1.4577x; 1.2712x over previous
#include <cuda_runtime.h>
#include <math.h>
#include <cstdint>

// Shape fixed by dataset: B=16, N=1024, E=128, kv row = 2E+1 = 257
#define BATCH   16
#define NATOMS  1024
#define EDIM    128
#define KVROW   257
#define TI      128
#define TJ      64
#define NTILES  16
#define THREADS 512

// Quantized operands: per row 128 int8 = 32 uint32. k_int = 128*hi + lo.
__device__ uint32_t g_khi[BATCH * NATOMS * 32];
__device__ uint32_t g_klo[BATCH * NATOMS * 32];
__device__ uint32_t g_vhi[BATCH * NATOMS * 32];
__device__ uint32_t g_vlo[BATCH * NATOMS * 32];
__device__ float    g_sk[BATCH * NATOMS];   // includes mask & 1/sqrt(E)
__device__ float    g_sv[BATCH * NATOMS];   // includes mask

// int8 rows: 128 B payload, stride 144 B -> ldmatrix 8-row phases cover all
// 32 banks exactly (16-byte steps of 4 banks). Conflict-free.
#define STRIDE_B 144

#define OFF_AHI  0                       // 128*144 = 18432
#define OFF_ALO  18432
#define OFF_B0HI 36864                   // 64*144 = 9216 each
#define OFF_B0LO 46080
#define OFF_B1HI 55296
#define OFF_B1LO 64512
#define OFF_PQ   73728                   // 4 stages x 64 x 16B = 4096
#define OFF_RED  77824                   // 4 col-groups x 128 rows x 3 floats
#define OFF_MS   83968                   // 16 floats
#define SMEM_BYTES 84032

__device__ __forceinline__ uint32_t smem_u32(const void* p) {
    uint32_t a;
    asm("{ .reg .u64 t; cvta.to.shared.u64 t, %1; cvt.u32.u64 %0, t; }"
        : "=r"(a) : "l"(p));
    return a;
}
__device__ __forceinline__ void cpa16(uint32_t dst, const void* src) {
    asm volatile("cp.async.cg.shared.global [%0], [%1], 16;" :: "r"(dst), "l"(src));
}
__device__ __forceinline__ void cpa4(uint32_t dst, const void* src) {
    asm volatile("cp.async.ca.shared.global [%0], [%1], 4;" :: "r"(dst), "l"(src));
}
#define CP_COMMIT() asm volatile("cp.async.commit_group;" ::: "memory")
#define CP_WAIT0()  asm volatile("cp.async.wait_group 0;" ::: "memory")

#define LDSM4(r, addr)                                                      \
    asm volatile("ldmatrix.sync.aligned.m8n8.x4.shared.b16 {%0,%1,%2,%3}, [%4];" \
        : "=r"((r)[0]), "=r"((r)[1]), "=r"((r)[2]), "=r"((r)[3]) : "r"(addr))

#define MMA_S8(c, a, b0_, b1_)                                              \
    asm volatile("mma.sync.aligned.m16n8k32.row.col.s32.s8.s8.s32 "         \
        "{%0,%1,%2,%3}, {%4,%5,%6,%7}, {%8,%9}, {%0,%1,%2,%3};"             \
        : "+r"((c)[0]), "+r"((c)[1]), "+r"((c)[2]), "+r"((c)[3])            \
        : "r"((a)[0]), "r"((a)[1]), "r"((a)[2]), "r"((a)[3]),               \
          "r"(b0_), "r"(b1_))

// ---------------- prepass: fp32 -> 15-bit fixed point, int8 hi/lo ----------
__global__ __launch_bounds__(256)
void quant_kv_kernel(const float* __restrict__ kv,
                     const float* __restrict__ mask)
{
    int gw = (blockIdx.x * 256 + threadIdx.x) >> 5;   // row id [0, B*N)
    if (gw >= BATCH * NATOMS) return;
    const int lane = threadIdx.x & 31;
    const float* row = kv + (size_t)gw * KVROW;
    const float m = mask[gw];

    #pragma unroll
    for (int part = 0; part < 2; part++) {            // 0 = K, 1 = V
        const float* src = row + part * EDIM + 4 * lane;
        float x0 = src[0] * m, x1 = src[1] * m, x2 = src[2] * m, x3 = src[3] * m;
        float amax = fmaxf(fmaxf(fabsf(x0), fabsf(x1)),
                           fmaxf(fabsf(x2), fabsf(x3)));
        #pragma unroll
        for (int off = 16; off > 0; off >>= 1)
            amax = fmaxf(amax, __shfl_xor_sync(0xFFFFFFFFu, amax, off));
        float inv = amax > 0.f ? 16256.f / amax : 0.f;

        int q0 = __float2int_rn(x0 * inv);
        int q1 = __float2int_rn(x1 * inv);
        int q2 = __float2int_rn(x2 * inv);
        int q3 = __float2int_rn(x3 * inv);
        int h0 = (q0 + 64) >> 7, h1 = (q1 + 64) >> 7;
        int h2 = (q2 + 64) >> 7, h3 = (q3 + 64) >> 7;
        int l0 = q0 - (h0 << 7), l1 = q1 - (h1 << 7);
        int l2 = q2 - (h2 << 7), l3 = q3 - (h3 << 7);
        uint32_t hi = (uint32_t)(h0 & 255) | ((uint32_t)(h1 & 255) << 8)
                    | ((uint32_t)(h2 & 255) << 16) | ((uint32_t)(h3 & 255) << 24);
        uint32_t lo = (uint32_t)(l0 & 255) | ((uint32_t)(l1 & 255) << 8)
                    | ((uint32_t)(l2 & 255) << 16) | ((uint32_t)(l3 & 255) << 24);
        if (part == 0) {
            g_khi[gw * 32 + lane] = hi;
            g_klo[gw * 32 + lane] = lo;
            if (lane == 0)
                g_sk[gw] = (amax * (1.f / 16256.f)) * 0.088388347648318447f;
        } else {
            g_vhi[gw * 32 + lane] = hi;
            g_vlo[gw * 32 + lane] = lo;
            if (lane == 0) g_sv[gw] = amax * (1.f / 16256.f);
        }
    }
}

// ---------------- main kernel: 16 warps, 4x4 grid of 32x16 warp tiles ------
__global__ __launch_bounds__(THREADS, 1)
void gen_actions_kernel(const float* __restrict__ pos,
                        const float* __restrict__ mask,
                        const float* __restrict__ ascale,
                        float* __restrict__ out)
{
    extern __shared__ char sp[];
    const uint32_t sb = smem_u32(sp);

    const int tid  = threadIdx.x;
    const int wid  = tid >> 5;
    const int lane = tid & 31;
    const int wr   = wid & 3;       // warp rows [32wr, 32wr+32)
    const int wc   = wid >> 2;      // warp cols [16wc, 16wc+16)
    const int qid  = lane >> 2;
    const int qe   = lane & 3;

    const int b  = blockIdx.y;
    const int i0 = blockIdx.x * TI;
    const int bN = b * NATOMS;

    const float* mb = mask + (size_t)bN;
    const float* pb = pos  + (size_t)bN * 3;

    // ---- prologue: A hi/lo + B tile 0 hi/lo + pos/scale stage 0 ----
    {
        const uint32_t* ah = g_khi + (size_t)(bN + i0) * 32;
        const uint32_t* al = g_klo + (size_t)(bN + i0) * 32;
        #pragma unroll
        for (int it = 0; it < 2; it++) {
            int idx = tid + it * THREADS;            // [0,1024): r=idx>>3,c=idx&7
            int r = idx >> 3, c = idx & 7;
            cpa16(sb + OFF_AHI + r * STRIDE_B + c * 16, ah + r * 32 + c * 4);
            cpa16(sb + OFF_ALO + r * STRIDE_B + c * 16, al + r * 32 + c * 4);
        }
        const uint32_t* bh = g_vhi + (size_t)bN * 32;   // jt = 0
        const uint32_t* bl = g_vlo + (size_t)bN * 32;
        {
            int r = tid >> 3, c = tid & 7;               // [0,512) = 64 rows x 8
            cpa16(sb + OFF_B0HI + r * STRIDE_B + c * 16, bh + r * 32 + c * 4);
            cpa16(sb + OFF_B0LO + r * STRIDE_B + c * 16, bl + r * 32 + c * 4);
        }
        if (tid < 256) {   // 64 rows x {x,y,z,sv}
            int r = tid >> 2, c = tid & 3;
            const float* src = (c < 3) ? pb + r * 3 + c : g_sv + bN + r;
            cpa4(sb + OFF_PQ + r * 16 + c * 4, src);
        }
        CP_COMMIT();
    }

    // ---- mask sum (overlaps the async loads) ----
    {
        float* sMS = (float*)(sp + OFF_MS);
        float ms = 0.f;
        for (int n = tid; n < NATOMS; n += THREADS) ms += mb[n];
        #pragma unroll
        for (int off = 16; off > 0; off >>= 1)
            ms += __shfl_xor_sync(0xFFFFFFFFu, ms, off);
        if (lane == 0) sMS[wid] = ms;
    }
    __syncthreads();
    float msum = 0.f;
    {
        float* sMS = (float*)(sp + OFF_MS);
        #pragma unroll
        for (int q = 0; q < 16; q++) msum += sMS[q];
    }
    const float inv_msum = 1.0f / msum;
    const float as = ascale[0];

    // ---- this thread's 4 fixed rows: 32wr + 16mt + 8h + qid ----
    float pix[4], piy[4], piz[4], skv[4];
    #pragma unroll
    for (int mt = 0; mt < 2; mt++)
        #pragma unroll
        for (int h = 0; h < 2; h++) {
            int ridx = 2 * mt + h;
            int gi = i0 + 32 * wr + 16 * mt + 8 * h + qid;
            const float* p = pb + (size_t)gi * 3;
            pix[ridx] = p[0]; piy[ridx] = p[1]; piz[ridx] = p[2];
            skv[ridx] = g_sk[bN + gi];
        }

    // ---- ldmatrix lane base addresses (conflict-free, stride 144) ----
    const uint32_t aRow = 32 * wr + (lane & 15);
    const uint32_t aKof = (lane & 16) ? 16u : 0u;
    const uint32_t aHiB = sb + OFF_AHI + aRow * STRIDE_B + aKof;
    const uint32_t aLoB = sb + OFF_ALO + aRow * STRIDE_B + aKof;
    const uint32_t bRow = 16 * wc + (lane & 7) + ((lane & 16) ? 8 : 0);
    const uint32_t bKof = (lane & 8) ? 16u : 0u;
    const uint32_t bLaneOff = bRow * STRIDE_B + bKof;

    float ax[4], ay[4], az[4];
    #pragma unroll
    for (int r = 0; r < 4; r++) { ax[r] = 0.f; ay[r] = 0.f; az[r] = 0.f; }

    for (int t = 0; t < NTILES; t++) {
        CP_WAIT0();
        __syncthreads();
        if (t + 1 < NTILES) {
            const int jn = (t + 1) * TJ;
            const uint32_t hiN = ((t + 1) & 1) ? OFF_B1HI : OFF_B0HI;
            const uint32_t loN = ((t + 1) & 1) ? OFF_B1LO : OFF_B0LO;
            const uint32_t* bh = g_vhi + (size_t)(bN + jn) * 32;
            const uint32_t* bl = g_vlo + (size_t)(bN + jn) * 32;
            {
                int r = tid >> 3, c = tid & 7;
                cpa16(sb + hiN + r * STRIDE_B + c * 16, bh + r * 32 + c * 4);
                cpa16(sb + loN + r * STRIDE_B + c * 16, bl + r * 32 + c * 4);
            }
            if (tid < 256) {
                int r = tid >> 2, c = tid & 3;
                const float* src = (c < 3) ? pb + (jn + r) * 3 + c
                                           : g_sv + bN + jn + r;
                cpa4(sb + OFF_PQ + (((t + 1) & 3) * 64 + r) * 16 + c * 4, src);
            }
            CP_COMMIT();
        }

        const uint32_t bHiB = sb + ((t & 1) ? OFF_B1HI : OFF_B0HI) + bLaneOff;
        const uint32_t bLoB = sb + ((t & 1) ? OFF_B1LO : OFF_B0LO) + bLaneOff;

        // ---- int8 GEMM: P1 = khi.vhi (weight 16384), P2 = khi.vlo + klo.vhi
        //      (weight 128). Exact s32 accumulation, K=32 per MMA.
        int C1[2][2][4], C2[2][2][4];
        #pragma unroll
        for (int mt = 0; mt < 2; mt++)
            #pragma unroll
            for (int nt = 0; nt < 2; nt++)
                #pragma unroll
                for (int e = 0; e < 4; e++) { C1[mt][nt][e] = 0; C2[mt][nt][e] = 0; }

        #pragma unroll
        for (int kc = 0; kc < 4; kc++) {
            uint32_t ah[2][4], al[2][4], bh[4], bl[4];
            const uint32_t ko = kc * 32;
            #pragma unroll
            for (int mt = 0; mt < 2; mt++) {
                uint32_t o = mt * (16 * STRIDE_B) + ko;
                LDSM4(ah[mt], aHiB + o);
                LDSM4(al[mt], aLoB + o);
            }
            LDSM4(bh, bHiB + ko);
            LDSM4(bl, bLoB + ko);
            #pragma unroll
            for (int mt = 0; mt < 2; mt++) {
                MMA_S8(C1[mt][0], ah[mt], bh[0], bh[1]);
                MMA_S8(C1[mt][1], ah[mt], bh[2], bh[3]);
            }
            #pragma unroll
            for (int mt = 0; mt < 2; mt++) {
                MMA_S8(C2[mt][0], ah[mt], bl[0], bl[1]);
                MMA_S8(C2[mt][1], ah[mt], bl[2], bl[3]);
            }
            #pragma unroll
            for (int mt = 0; mt < 2; mt++) {
                MMA_S8(C2[mt][0], al[mt], bh[0], bh[1]);
                MMA_S8(C2[mt][1], al[mt], bh[2], bh[3]);
            }
        }

        // ---- fused epilogue: S = sk_i*sv_j*(16384*P1 + 128*P2) ----
        const float4* sQ = (const float4*)(sp + OFF_PQ + (t & 3) * 1024);
        #pragma unroll
        for (int mt = 0; mt < 2; mt++)
            #pragma unroll
            for (int h = 0; h < 2; h++) {
                int ridx = 2 * mt + h;
                float px = pix[ridx], py = piy[ridx], pz = piz[ridx];
                float skr = skv[ridx];
                #pragma unroll
                for (int nt = 0; nt < 2; nt++)
                    #pragma unroll
                    for (int e = 0; e < 2; e++) {
                        float4 q = sQ[16 * wc + 8 * nt + 2 * qe + e];
                        float dx = px - q.x;
                        float dy = py - q.y;
                        float dz = pz - q.z;
                        float d2 = fmaf(dx, dx, fmaf(dy, dy, dz * dz));
                        float inv = rsqrtf(fmaxf(d2, 1e-36f));   // diag -> 0
                        float comb = fmaf(16384.f,
                                          (float)C1[mt][nt][2 * h + e],
                                          128.f * (float)C2[mt][nt][2 * h + e]);
                        float w = skr * q.w * comb * inv;
                        ax[ridx] = fmaf(w, dx, ax[ridx]);
                        ay[ridx] = fmaf(w, dy, ay[ridx]);
                        az[ridx] = fmaf(w, dz, az[ridx]);
                    }
            }
    }

    // ---- reduce over qe lanes (bits 0,1): sums this warp's 16 cols ----
    #pragma unroll
    for (int off = 1; off < 4; off <<= 1)
        #pragma unroll
        for (int r = 0; r < 4; r++) {
            ax[r] += __shfl_xor_sync(0xFFFFFFFFu, ax[r], off);
            ay[r] += __shfl_xor_sync(0xFFFFFFFFu, ay[r], off);
            az[r] += __shfl_xor_sync(0xFFFFFFFFu, az[r], off);
        }

    __syncthreads();
    float* sRed = (float*)(sp + OFF_RED);    // [4 col-groups][128 rows][3]
    if (qe == 0) {
        #pragma unroll
        for (int mt = 0; mt < 2; mt++)
            #pragma unroll
            for (int h = 0; h < 2; h++) {
                int row = 32 * wr + 16 * mt + 8 * h + qid;
                float* d = sRed + (wc * 128 + row) * 3;
                int ridx = 2 * mt + h;
                d[0] = ax[ridx]; d[1] = ay[ridx]; d[2] = az[ridx];
            }
    }
    __syncthreads();

    if (tid < TI) {
        int gi = i0 + tid;
        float sx = 0.f, sy = 0.f, sz = 0.f;
        #pragma unroll
        for (int g = 0; g < 4; g++) {
            const float* d = sRed + (g * 128 + tid) * 3;
            sx += d[0]; sy += d[1]; sz += d[2];
        }
        float s = as * mb[gi];
        float* o = out + ((size_t)bN + gi) * 3;
        o[0] = tanhf(sx * inv_msum) * s;
        o[1] = tanhf(sy * inv_msum) * s;
        o[2] = tanhf(sz * inv_msum) * s;
    }
}

extern "C" void kernel_launch(void* const* d_in, const int* in_sizes, int n_in,
                              void* d_out, int out_size) {
    const float* kv   = (const float*)d_in[0];
    const float* pos  = (const float*)d_in[1];
    const float* mask = (const float*)d_in[2];
    const float* asc  = (const float*)d_in[3];
    float* out = (float*)d_out;

    cudaFuncSetAttribute(gen_actions_kernel,
                         cudaFuncAttributeMaxDynamicSharedMemorySize,
                         (int)SMEM_BYTES);

    // 16384 rows, one warp per row (handles both K and V segments)
    quant_kv_kernel<<<(BATCH * NATOMS * 32 + 255) / 256, 256>>>(kv, mask);

    dim3 grid(NATOMS / TI, BATCH);   // 8 x 16 = 128 blocks, one wave
    gen_actions_kernel<<<grid, THREADS, SMEM_BYTES>>>(pos, mask, asc, out);
}